// round 12
// baseline (speedup 1.0000x reference)
#include <cuda_runtime.h>
#include <math.h>
#include <float.h>

// ---------------- problem constants ----------------
#define NB    8
#define NPTS  8192
#define MQ    1024
#define KNN   17
#define NPB   (NB*NPTS)        // 65536 points total
#define NQ    (NB*MQ)          // 8192 queries total
#define NPOS  (NQ*KNN)         // 139264 (m,k) positions
#define FULLM 0xffffffffu

// ---------------- scratch (device globals; no allocs allowed) ----------------
__device__ float g_h1 [NPB*64];
__device__ float g_t  [NPB*256];
__device__ float g_f  [NPB*128];     // (b*NPTS+n, 128)
__device__ float g_sx [NPB];
__device__ int   g_fps[NQ];
__device__ int   g_knn[NQ*KNN];
__device__ float g_r  [NPOS*9];
__device__ float g_hb1[NPOS*64];
__device__ float g_hb2[NPOS*64];
__device__ float g_r2 [NPOS*128];
__device__ float g_feat0[NQ*256];
__device__ float g_q  [NQ*256];
__device__ float g_u  [NQ*256];
__device__ float g_cb [NB*256];
__device__ float g_Wa [256*64];
__device__ float g_ba [256];
__device__ float g_kwT[256*256];

// ---------------- per-batch global-feature MLP + cs bias fold ----------------
__global__ void k_pre_batch(const float* __restrict__ gf,
                            const float* __restrict__ w1, const float* __restrict__ b1,
                            const float* __restrict__ w2, const float* __restrict__ b2,
                            const float* __restrict__ csw1, const float* __restrict__ csb1)
{
    __shared__ float s_gf[512];
    __shared__ float s_h[256];
    __shared__ float s_g[128];
    int b = blockIdx.x, t = threadIdx.x;
    s_gf[t]       = gf[b*512 + t];
    s_gf[t + 256] = gf[b*512 + 256 + t];
    __syncthreads();
    float acc = b1[t];
    for (int c = 0; c < 512; ++c) acc += w1[t*512 + c] * s_gf[c];
    s_h[t] = fmaxf(acc, 0.f);
    __syncthreads();
    if (t < 128) {
        float a = b2[t];
        for (int c = 0; c < 256; ++c) a += w2[t*256 + c] * s_h[c];
        s_g[t] = a;
    }
    __syncthreads();
    float a = csb1[t];
    for (int c = 0; c < 128; ++c) a += csw1[t*256 + 128 + c] * s_g[c];
    g_cb[b*256 + t] = a;
}

// ---------------- fold Wa = cs_w1[:, :128] @ c1_w2 ; ba ; k_w transpose -------
__global__ void k_pre_fold(const float* __restrict__ csw1,
                           const float* __restrict__ c1w2,
                           const float* __restrict__ c1b2,
                           const float* __restrict__ kw)
{
    int i = blockIdx.x*256 + threadIdx.x;
    if (i < 16384) {
        int o = i >> 6, c = i & 63;
        float a = 0.f;
        for (int k = 0; k < 128; ++k) a += csw1[o*256 + k] * c1w2[k*64 + c];
        g_Wa[o*64 + c] = a;
    } else if (i < 16640) {
        int o = i - 16384;
        float a = 0.f;
        for (int k = 0; k < 128; ++k) a += csw1[o*256 + k] * c1b2[k];
        g_ba[o] = a;
    } else if (i < 16640 + 65536) {
        int j = i - 16640;
        int o = j >> 8, c = j & 255;
        g_kwT[c*256 + o] = kw[o*256 + c];
    }
}

// ---------------- h1 = relu(c1_w1 x + c1_b1), plus per-point sum of squares ---
__global__ void k_h1(const float* __restrict__ x,
                     const float* __restrict__ w1, const float* __restrict__ b1)
{
    __shared__ float sw[192];
    __shared__ float sb[64];
    int t = threadIdx.x;
    for (int i = t; i < 192; i += 128) sw[i] = w1[i];
    if (t < 64) sb[t] = b1[t];
    __syncthreads();
    int p = blockIdx.x*128 + t;
    float x0 = x[p*3 + 0], x1 = x[p*3 + 1], x2 = x[p*3 + 2];
    g_sx[p] = __fadd_rn(__fadd_rn(__fmul_rn(x0, x0), __fmul_rn(x1, x1)), __fmul_rn(x2, x2));
    #pragma unroll 8
    for (int o = 0; o < 64; ++o) {
        float h = sb[o] + sw[o*3]*x0 + sw[o*3+1]*x1 + sw[o*3+2]*x2;
        g_h1[p*64 + o] = fmaxf(h, 0.f);
    }
}

// ---------------- generic tiled SGEMM: Y[p][o] = sum_c W[o][c] X[p][c] -------
// modes: 0 plain, 1 +bias, 2 relu(+bias+extra[(p>>sh)*ld+o]), 3 lrelu(bn(+bias))
__global__ __launch_bounds__(256)
void k_gemm(const float* __restrict__ W, const float* __restrict__ X,
            float* __restrict__ Y, const float* __restrict__ bias,
            const float* __restrict__ extra, int extraShift, int extraLd,
            const float* __restrict__ bnG, const float* __restrict__ bnB,
            int C, int O, int mode)
{
    __shared__ float Ws[16][68];
    __shared__ float Xs[16][68];
    int tid = threadIdx.x;
    int tx = tid & 15, ty = tid >> 4;
    int pT = blockIdx.x * 64, oT = blockIdx.y * 64;
    float acc[4][4];
    #pragma unroll
    for (int i = 0; i < 4; ++i)
        #pragma unroll
        for (int j = 0; j < 4; ++j) acc[i][j] = 0.f;

    for (int c0 = 0; c0 < C; c0 += 16) {
        #pragma unroll
        for (int i = 0; i < 4; ++i) {
            int e = i*256 + tid;
            int cc = e & 15, r = e >> 4;
            Ws[cc][r] = W[(oT + r)*C + c0 + cc];
            Xs[cc][r] = X[(pT + r)*C + c0 + cc];
        }
        __syncthreads();
        #pragma unroll
        for (int cc = 0; cc < 16; ++cc) {
            float4 wv = *reinterpret_cast<const float4*>(&Ws[cc][tx*4]);
            float4 xv = *reinterpret_cast<const float4*>(&Xs[cc][ty*4]);
            acc[0][0] = fmaf(xv.x, wv.x, acc[0][0]);
            acc[0][1] = fmaf(xv.x, wv.y, acc[0][1]);
            acc[0][2] = fmaf(xv.x, wv.z, acc[0][2]);
            acc[0][3] = fmaf(xv.x, wv.w, acc[0][3]);
            acc[1][0] = fmaf(xv.y, wv.x, acc[1][0]);
            acc[1][1] = fmaf(xv.y, wv.y, acc[1][1]);
            acc[1][2] = fmaf(xv.y, wv.z, acc[1][2]);
            acc[1][3] = fmaf(xv.y, wv.w, acc[1][3]);
            acc[2][0] = fmaf(xv.z, wv.x, acc[2][0]);
            acc[2][1] = fmaf(xv.z, wv.y, acc[2][1]);
            acc[2][2] = fmaf(xv.z, wv.z, acc[2][2]);
            acc[2][3] = fmaf(xv.z, wv.w, acc[2][3]);
            acc[3][0] = fmaf(xv.w, wv.x, acc[3][0]);
            acc[3][1] = fmaf(xv.w, wv.y, acc[3][1]);
            acc[3][2] = fmaf(xv.w, wv.z, acc[3][2]);
            acc[3][3] = fmaf(xv.w, wv.w, acc[3][3]);
        }
        __syncthreads();
    }

    const float bnsc = 1.f / sqrtf(1.0f + 1e-5f);
    int p0 = pT + ty*4;
    int o0 = oT + tx*4;
    #pragma unroll
    for (int i = 0; i < 4; ++i) {
        float vs[4];
        #pragma unroll
        for (int j = 0; j < 4; ++j) {
            float v = acc[i][j];
            int og = o0 + j;
            if (mode >= 1) v += bias[og];
            if (mode == 2) {
                v += extra[((p0 + i) >> extraShift)*extraLd + og];
                v = fmaxf(v, 0.f);
            } else if (mode == 3) {
                v = v * (bnG[og] * bnsc) + bnB[og];
                v = (v > 0.f) ? v : 0.01f * v;
            }
            vs[j] = v;
        }
        *reinterpret_cast<float4*>(&Y[(p0 + i)*O + o0]) =
            make_float4(vs[0], vs[1], vs[2], vs[3]);
    }
}

// ---------------- FPS: one block per batch, points+mind in regs, smem bcast ---
__global__ __launch_bounds__(1024)
void k_fps(const float* __restrict__ x, float* __restrict__ out)
{
    extern __shared__ float sm[];
    float* s_px = sm;
    float* s_py = sm + NPTS;
    float* s_pz = sm + 2*NPTS;
    __shared__ float s_wv[32];
    __shared__ int   s_wi[32];
    __shared__ int   s_sel;

    int b = blockIdx.x, t = threadIdx.x;
    int lane = t & 31, warp = t >> 5;
    int base = t * 8;

    float rx[8], ry[8], rz[8], md[8];
    #pragma unroll
    for (int i = 0; i < 8; ++i) {
        int n = base + i;
        const float* p = &x[(b*NPTS + n)*3];
        rx[i] = p[0]; ry[i] = p[1]; rz[i] = p[2];
        s_px[n] = rx[i]; s_py[n] = ry[i]; s_pz[n] = rz[i];
        md[i] = 1e10f;
    }
    if (t == 0) {
        s_sel = 0;
        g_fps[b*MQ] = 0;
        float* o = &out[(b*MQ)*3];
        o[0] = rx[0]; o[1] = ry[0]; o[2] = rz[0];
    }
    __syncthreads();

    for (int it = 1; it < MQ; ++it) {
        int sel = s_sel;
        float lx = s_px[sel], ly = s_py[sel], lz = s_pz[sel];
        float bv = -1e30f; int bi = 0x7fffffff;
        #pragma unroll
        for (int i = 0; i < 8; ++i) {
            float dx = __fsub_rn(rx[i], lx);
            float dy = __fsub_rn(ry[i], ly);
            float dz = __fsub_rn(rz[i], lz);
            float d  = __fadd_rn(__fadd_rn(__fmul_rn(dx, dx), __fmul_rn(dy, dy)),
                                 __fmul_rn(dz, dz));
            float m2 = fminf(md[i], d);
            md[i] = m2;
            if (m2 > bv) { bv = m2; bi = base + i; }
        }
        #pragma unroll
        for (int off = 16; off > 0; off >>= 1) {
            float ov = __shfl_down_sync(FULLM, bv, off);
            int   oi = __shfl_down_sync(FULLM, bi, off);
            if (ov > bv || (ov == bv && oi < bi)) { bv = ov; bi = oi; }
        }
        if (lane == 0) { s_wv[warp] = bv; s_wi[warp] = bi; }
        __syncthreads();
        if (warp == 0) {
            bv = s_wv[lane]; bi = s_wi[lane];
            #pragma unroll
            for (int off = 16; off > 0; off >>= 1) {
                float ov = __shfl_down_sync(FULLM, bv, off);
                int   oi = __shfl_down_sync(FULLM, bi, off);
                if (ov > bv || (ov == bv && oi < bi)) { bv = ov; bi = oi; }
            }
            if (lane == 0) {
                s_sel = bi;
                g_fps[b*MQ + it] = bi;
                float* o = &out[(b*MQ + it)*3];
                o[0] = s_px[bi]; o[1] = s_py[bi]; o[2] = s_pz[bi];
            }
        }
        __syncthreads();
    }
}

// ---------------- KNN: warp per query; per-lane sorted top-17 + warp merge ----
__global__ __launch_bounds__(256)
void k_knn(const float* __restrict__ x)
{
    int wq = blockIdx.x*8 + (threadIdx.x >> 5);
    int lane = threadIdx.x & 31;
    int b = wq >> 10;
    int self = g_fps[wq];
    const float* qp = &x[(b*NPTS + self)*3];
    float qx = qp[0], qy = qp[1], qz = qp[2];
    float qs = g_sx[b*NPTS + self];

    float v[KNN]; int id[KNN];
    #pragma unroll
    for (int j = 0; j < KNN; ++j) { v[j] = FLT_MAX; id[j] = 0x7fffffff; }

    for (int n = lane; n < NPTS; n += 32) {
        const float* p = &x[(b*NPTS + n)*3];
        float dot = __fadd_rn(__fadd_rn(__fmul_rn(qx, p[0]), __fmul_rn(qy, p[1])),
                              __fmul_rn(qz, p[2]));
        float sn = g_sx[b*NPTS + n];
        float d2 = __fsub_rn(__fadd_rn(qs, sn), __fmul_rn(2.0f, dot));
        if (d2 < v[KNN-1] || (d2 == v[KNN-1] && n < id[KNN-1])) {
            v[KNN-1] = d2; id[KNN-1] = n;
            #pragma unroll
            for (int j = KNN-1; j > 0; --j) {
                if (v[j] < v[j-1] || (v[j] == v[j-1] && id[j] < id[j-1])) {
                    float tv = v[j]; v[j] = v[j-1]; v[j-1] = tv;
                    int   ti = id[j]; id[j] = id[j-1]; id[j-1] = ti;
                }
            }
        }
    }
    // merge: 17 rounds of warp-argmin on each lane's head
    for (int r = 0; r < KNN; ++r) {
        float cv = v[0]; int ci = id[0];
        float bv = cv;   int bi = ci;
        #pragma unroll
        for (int off = 16; off > 0; off >>= 1) {
            float ov = __shfl_xor_sync(FULLM, bv, off);
            int   oi = __shfl_xor_sync(FULLM, bi, off);
            if (ov < bv || (ov == bv && oi < bi)) { bv = ov; bi = oi; }
        }
        if (cv == bv && ci == bi) {   // winner lane pops its head
            #pragma unroll
            for (int j = 0; j < KNN-1; ++j) { v[j] = v[j+1]; id[j] = id[j+1]; }
            v[KNN-1] = FLT_MAX; id[KNN-1] = 0x7fffffff;
        }
        if (lane == 0) g_knn[wq*KNN + r] = bi;
    }
}

// ---------------- build r = [rep, knn, rep-knn] per (m,k) ---------------------
__global__ void k_build_r(const float* __restrict__ x)
{
    int i = blockIdx.x*256 + threadIdx.x;
    if (i >= NPOS) return;
    int q = i / KNN;
    int b = q >> 10;
    int dn = g_fps[q];
    int nn = g_knn[i];
    const float* dp = &x[(b*NPTS + dn)*3];
    const float* kp = &x[(b*NPTS + nn)*3];
    float* r = &g_r[i*9];
    r[0] = dp[0]; r[1] = dp[1]; r[2] = dp[2];
    r[3] = kp[0]; r[4] = kp[1]; r[5] = kp[2];
    r[6] = dp[0]-kp[0]; r[7] = dp[1]-kp[1]; r[8] = dp[2]-kp[2];
}

// ---------------- s2 layer1: 9->64, bn + leaky --------------------------------
__global__ void k_s2l1(const float* __restrict__ w, const float* __restrict__ bias,
                       const float* __restrict__ bg, const float* __restrict__ bb)
{
    __shared__ float sw[576];
    __shared__ float sb[64], sg[64], sbb[64];
    int t = threadIdx.x;
    for (int i = t; i < 576; i += 128) sw[i] = w[i];
    if (t < 64) { sb[t] = bias[t]; sg[t] = bg[t]; sbb[t] = bb[t]; }
    __syncthreads();
    int p = blockIdx.x*128 + t;
    float rr[9];
    #pragma unroll
    for (int c = 0; c < 9; ++c) rr[c] = g_r[p*9 + c];
    const float bnsc = 1.f / sqrtf(1.0f + 1e-5f);
    #pragma unroll 4
    for (int o = 0; o < 64; ++o) {
        float a = sb[o];
        #pragma unroll
        for (int c = 0; c < 9; ++c) a = fmaf(sw[o*9 + c], rr[c], a);
        a = a * (sg[o] * bnsc) + sbb[o];
        a = (a > 0.f) ? a : 0.01f * a;
        g_hb1[p*64 + o] = a;
    }
}

// ---------------- feat0 gather (self neighbor features) -----------------------
__global__ void k_feat0()
{
    int i = blockIdx.x*256 + threadIdx.x;
    int q = i >> 8, c = i & 255;
    int b = q >> 10;
    float val;
    if (c < 128) {
        int n = g_knn[q*KNN];
        val = g_f[(b*NPTS + n)*128 + c];
    } else {
        val = g_r2[(q*KNN)*128 + (c - 128)];
    }
    g_feat0[i] = val;
}

// ---------------- attention: logits via u.feat, softmax, weighted sum --------
__global__ __launch_bounds__(256)
void k_att(const float* __restrict__ x, const float* __restrict__ kb,
           float* __restrict__ out)
{
    int wq = blockIdx.x*8 + (threadIdx.x >> 5);
    int lane = threadIdx.x & 31;
    int b = wq >> 10;

    const float* u  = &g_u[wq*256];
    const float* qv = &g_q[wq*256];
    float uf[4], ur[4];
    #pragma unroll
    for (int t = 0; t < 4; ++t) { uf[t] = u[lane + 32*t]; ur[t] = u[128 + lane + 32*t]; }
    float cc = 0.f;
    #pragma unroll
    for (int t = 0; t < 8; ++t) cc += qv[lane + 32*t] * kb[lane + 32*t];
    #pragma unroll
    for (int off = 16; off > 0; off >>= 1) cc += __shfl_xor_sync(FULLM, cc, off);

    float logit = 0.f;
    for (int j = 1; j < KNN; ++j) {
        int n = g_knn[wq*KNN + j];
        const float* fp = &g_f[(b*NPTS + n)*128];
        const float* rp = &g_r2[(wq*KNN + j)*128];
        float a = 0.f;
        #pragma unroll
        for (int t = 0; t < 4; ++t) a = fmaf(uf[t], fp[lane + 32*t], a);
        #pragma unroll
        for (int t = 0; t < 4; ++t) a = fmaf(ur[t], rp[lane + 32*t], a);
        #pragma unroll
        for (int off = 16; off > 0; off >>= 1) a += __shfl_xor_sync(FULLM, a, off);
        if (lane == j - 1) logit = a + cc;
    }
    float lv = (lane < 16) ? logit : -FLT_MAX;
    float mx = lv;
    #pragma unroll
    for (int off = 16; off > 0; off >>= 1) mx = fmaxf(mx, __shfl_xor_sync(FULLM, mx, off));
    float e = (lane < 16) ? expf(lv - mx) : 0.f;
    float s = e;
    #pragma unroll
    for (int off = 16; off > 0; off >>= 1) s += __shfl_xor_sync(FULLM, s, off);
    float w = e / s;

    float ox = 0.f, oy = 0.f, oz = 0.f;
    if (lane < 16) {
        int n = g_knn[wq*KNN + 1 + lane];
        const float* p = &x[(b*NPTS + n)*3];
        ox = w * p[0]; oy = w * p[1]; oz = w * p[2];
    }
    #pragma unroll
    for (int off = 16; off > 0; off >>= 1) {
        ox += __shfl_xor_sync(FULLM, ox, off);
        oy += __shfl_xor_sync(FULLM, oy, off);
        oz += __shfl_xor_sync(FULLM, oz, off);
    }
    if (lane == 0) {
        float* o = &out[(NQ + wq)*3];
        o[0] = ox; o[1] = oy; o[2] = oz;
    }
}

// ---------------- host side ---------------------------------------------------
static float* symf(const void* s) { void* p = 0; cudaGetSymbolAddress(&p, s); return (float*)p; }

extern "C" void kernel_launch(void* const* d_in, const int* in_sizes, int n_in,
                              void* d_out, int out_size)
{
    const float* x     = (const float*)d_in[0];
    const float* gfeat = (const float*)d_in[1];
    const float* c1_w1 = (const float*)d_in[2];
    const float* c1_b1 = (const float*)d_in[3];
    const float* c1_w2 = (const float*)d_in[4];
    const float* c1_b2 = (const float*)d_in[5];
    const float* cf_w1 = (const float*)d_in[6];
    const float* cf_b1 = (const float*)d_in[7];
    const float* cf_w2 = (const float*)d_in[8];
    const float* cf_b2 = (const float*)d_in[9];
    const float* cs_w1 = (const float*)d_in[10];
    const float* cs_b1 = (const float*)d_in[11];
    const float* cs_w2 = (const float*)d_in[12];
    const float* cs_b2 = (const float*)d_in[13];
    const float* s2_w1 = (const float*)d_in[14];
    const float* s2_b1 = (const float*)d_in[15];
    const float* s2_g1 = (const float*)d_in[16];
    const float* s2_bb1= (const float*)d_in[17];
    const float* s2_w2 = (const float*)d_in[18];
    const float* s2_b2 = (const float*)d_in[19];
    const float* s2_g2 = (const float*)d_in[20];
    const float* s2_bb2= (const float*)d_in[21];
    const float* s2_w3 = (const float*)d_in[22];
    const float* s2_b3 = (const float*)d_in[23];
    const float* q_w   = (const float*)d_in[24];
    const float* q_b   = (const float*)d_in[25];
    const float* k_w   = (const float*)d_in[26];
    const float* k_b   = (const float*)d_in[27];
    float* out = (float*)d_out;

    float* p_h1  = symf(g_h1);
    float* p_t   = symf(g_t);
    float* p_f   = symf(g_f);
    float* p_hb1 = symf(g_hb1);
    float* p_hb2 = symf(g_hb2);
    float* p_r2  = symf(g_r2);
    float* p_f0  = symf(g_feat0);
    float* p_q   = symf(g_q);
    float* p_u   = symf(g_u);
    float* p_cb  = symf(g_cb);
    float* p_Wa  = symf(g_Wa);
    float* p_ba  = symf(g_ba);
    float* p_kwT = symf(g_kwT);

    static int smem_set = 0;
    if (!smem_set) {
        cudaFuncSetAttribute(k_fps, cudaFuncAttributeMaxDynamicSharedMemorySize, 3*NPTS*4);
        smem_set = 1;
    }

    // FPS first (longest serial chain), then the rest of the pipeline.
    k_fps<<<NB, 1024, 3*NPTS*4>>>(x, out);

    k_pre_batch<<<NB, 256>>>(gfeat, cf_w1, cf_b1, cf_w2, cf_b2, cs_w1, cs_b1);
    k_pre_fold<<<321, 256>>>(cs_w1, c1_w2, c1_b2, k_w);
    k_h1<<<NPB/128, 128>>>(x, c1_w1, c1_b1);

    // t = relu(Wa @ h1 + ba + cb[batch])   (NPB x 256)
    k_gemm<<<dim3(NPB/64, 4), 256>>>(p_Wa, p_h1, p_t, p_ba,
                                     p_cb, 13, 256, nullptr, nullptr, 64, 256, 2);
    // f = cs_w2 @ t + cs_b2                (NPB x 128)
    k_gemm<<<dim3(NPB/64, 2), 256>>>(cs_w2, p_t, p_f, cs_b2,
                                     nullptr, 0, 0, nullptr, nullptr, 256, 128, 1);

    k_knn<<<NQ/8, 256>>>(x);
    k_build_r<<<(NPOS + 255)/256, 256>>>(x);
    k_s2l1<<<NPOS/128, 128>>>(s2_w1, s2_b1, s2_g1, s2_bb1);

    // hb2 = lrelu(bn(s2_w2 @ hb1 + s2_b2)) (NPOS x 64)
    k_gemm<<<dim3(NPOS/64, 1), 256>>>(s2_w2, p_hb1, p_hb2, s2_b2,
                                      nullptr, 0, 0, s2_g2, s2_bb2, 64, 64, 3);
    // r2 = s2_w3 @ hb2 + s2_b3             (NPOS x 128)
    k_gemm<<<dim3(NPOS/64, 2), 256>>>(s2_w3, p_hb2, p_r2, s2_b3,
                                      nullptr, 0, 0, nullptr, nullptr, 64, 128, 1);

    k_feat0<<<NQ*256/256, 256>>>();

    // q = q_w @ feat0 + q_b                (NQ x 256)
    k_gemm<<<dim3(NQ/64, 4), 256>>>(q_w, p_f0, p_q, q_b,
                                    nullptr, 0, 0, nullptr, nullptr, 256, 256, 1);
    // u = k_w^T @ q                        (NQ x 256)
    k_gemm<<<dim3(NQ/64, 4), 256>>>(p_kwT, p_q, p_u, nullptr,
                                    nullptr, 0, 0, nullptr, nullptr, 256, 256, 0);

    k_att<<<NQ/8, 256>>>(x, k_b, out);
}

// round 15
// speedup vs baseline: 1.2984x; 1.2984x over previous
#include <cuda_runtime.h>
#include <math.h>
#include <float.h>

// ---------------- problem constants ----------------
#define NB    8
#define NPTS  8192
#define MQ    1024
#define KNN   17
#define NPB   (NB*NPTS)        // 65536 points total
#define NQ    (NB*MQ)          // 8192 queries total
#define NPOS  (NQ*KNN)         // 139264 (m,k) positions
#define FULLM 0xffffffffu

typedef unsigned long long u64;

// ---------------- packed f32x2 helpers (Blackwell) ----------------
__device__ __forceinline__ u64 pack2(float lo, float hi) {
    u64 r; asm("mov.b64 %0, {%1, %2};" : "=l"(r) : "f"(lo), "f"(hi)); return r;
}
__device__ __forceinline__ void unpack2(float& lo, float& hi, u64 v) {
    asm("mov.b64 {%0, %1}, %2;" : "=f"(lo), "=f"(hi) : "l"(v));
}
__device__ __forceinline__ u64 add2(u64 a, u64 b) {
    u64 r; asm("add.rn.f32x2 %0, %1, %2;" : "=l"(r) : "l"(a), "l"(b)); return r;
}
__device__ __forceinline__ u64 mul2(u64 a, u64 b) {
    u64 r; asm("mul.rn.f32x2 %0, %1, %2;" : "=l"(r) : "l"(a), "l"(b)); return r;
}
__device__ __forceinline__ void fma2(u64& d, u64 a, u64 b) {
    asm("fma.rn.f32x2 %0, %1, %2, %0;" : "+l"(d) : "l"(a), "l"(b));
}

// ---------------- scratch (device globals; no allocs allowed) ----------------
__device__ float g_h1 [NPB*64];
__device__ float g_t  [NPB*256];
__device__ float g_f  [NPB*128];
__device__ int   g_fps[NQ];
__device__ int   g_knn[NQ*KNN];
__device__ float g_hb1[NPOS*64];
__device__ float g_hb2[NPOS*64];
__device__ float g_r2 [NPOS*128];
__device__ float g_feat0[NQ*256];
__device__ float g_u  [NQ*256];
__device__ float g_cb [NB*256];
__device__ float g_Wa [256*64];
__device__ float g_ba [256];
__device__ float g_A  [256*256];
__device__ float g_u0 [256];
__device__ float g_wc [256];
__device__ float g_c0;

// ---------------- per-batch global-feature MLP + cs bias fold ----------------
__global__ void k_pre_batch(const float* __restrict__ gf,
                            const float* __restrict__ w1, const float* __restrict__ b1,
                            const float* __restrict__ w2, const float* __restrict__ b2,
                            const float* __restrict__ csw1, const float* __restrict__ csb1)
{
    __shared__ float s_gf[512];
    __shared__ float s_h[256];
    __shared__ float s_g[128];
    int b = blockIdx.x, t = threadIdx.x;
    s_gf[t]       = gf[b*512 + t];
    s_gf[t + 256] = gf[b*512 + 256 + t];
    __syncthreads();
    float acc = b1[t];
    for (int c = 0; c < 512; ++c) acc += w1[t*512 + c] * s_gf[c];
    s_h[t] = fmaxf(acc, 0.f);
    __syncthreads();
    if (t < 128) {
        float a = b2[t];
        for (int c = 0; c < 256; ++c) a += w2[t*256 + c] * s_h[c];
        s_g[t] = a;
    }
    __syncthreads();
    float a = csb1[t];
    for (int c = 0; c < 128; ++c) a += csw1[t*256 + 128 + c] * s_g[c];
    g_cb[b*256 + t] = a;
}

// ---------------- fold Wa = cs_w1[:, :128] @ c1_w2 ; ba ------------------------
__global__ void k_pre_fold(const float* __restrict__ csw1,
                           const float* __restrict__ c1w2,
                           const float* __restrict__ c1b2)
{
    int i = blockIdx.x*256 + threadIdx.x;
    if (i < 16384) {
        int o = i >> 6, c = i & 63;
        float a = 0.f;
        for (int k = 0; k < 128; ++k) a += csw1[o*256 + k] * c1w2[k*64 + c];
        g_Wa[o*64 + c] = a;
    } else if (i < 16640) {
        int o = i - 16384;
        float a = 0.f;
        for (int k = 0; k < 128; ++k) a += csw1[o*256 + k] * c1b2[k];
        g_ba[o] = a;
    }
}

// ---------------- attention weight folds: A=k_w^T q_w, u0, w_c, c0 -----------
__global__ void k_pre_att(const float* __restrict__ qw, const float* __restrict__ qb,
                          const float* __restrict__ kw, const float* __restrict__ kb)
{
    __shared__ float sc[256];
    __shared__ float sqb[256], skb[256];
    int t = threadIdx.x, bx = blockIdx.x;
    if (bx < 256) {
        sc[t] = kw[t*256 + bx];          // k_w[o][bx], o=t
        __syncthreads();
        float a = 0.f;
        for (int o = 0; o < 256; ++o) a += sc[o] * qw[o*256 + t];
        g_A[bx*256 + t] = a;             // A[c=bx][d=t]
    } else {
        sqb[t] = qb[t]; skb[t] = kb[t];
        __syncthreads();
        float a = 0.f, w = 0.f;
        for (int o = 0; o < 256; ++o) {
            a += kw[o*256 + t] * sqb[o];
            w += qw[o*256 + t] * skb[o];
        }
        g_u0[t] = a; g_wc[t] = w;
        if (t == 0) {
            float c = 0.f;
            for (int o = 0; o < 256; ++o) c += sqb[o] * skb[o];
            g_c0 = c;
        }
    }
}

// ---------------- h1 = relu(c1_w1 x + c1_b1) ---------------------------------
__global__ void k_h1(const float* __restrict__ x,
                     const float* __restrict__ w1, const float* __restrict__ b1)
{
    __shared__ float sw[192];
    __shared__ float sb[64];
    int t = threadIdx.x;
    for (int i = t; i < 192; i += 128) sw[i] = w1[i];
    if (t < 64) sb[t] = b1[t];
    __syncthreads();
    int p = blockIdx.x*128 + t;
    float x0 = x[p*3 + 0], x1 = x[p*3 + 1], x2 = x[p*3 + 2];
    #pragma unroll 8
    for (int o = 0; o < 64; ++o) {
        float h = sb[o] + sw[o*3]*x0 + sw[o*3+1]*x1 + sw[o*3+2]*x2;
        g_h1[p*64 + o] = fmaxf(h, 0.f);
    }
}

// ---------------- 128x64 tiled SGEMM with FFMA2: Y[p][o]=sum_c W[o][c]X[p][c] -
// modes: 0 plain, 1 +bias, 2 relu(+bias+extra[(p>>sh)*ld+o]), 3 lrelu(bn(+bias))
__global__ __launch_bounds__(256)
void k_gemm(const float* __restrict__ W, const float* __restrict__ X,
            float* __restrict__ Y, const float* __restrict__ bias,
            const float* __restrict__ extra, int extraShift, int extraLd,
            const float* __restrict__ bnG, const float* __restrict__ bnB,
            int C, int O, int mode)
{
    __shared__ float Ws[16][68];
    __shared__ float Xs[16][132];
    int tid = threadIdx.x;
    int tx = tid & 15, ty = tid >> 4;
    int pT = blockIdx.x * 128, oT = blockIdx.y * 64;
    u64 acc[8][2];
    #pragma unroll
    for (int i = 0; i < 8; ++i) { acc[i][0] = 0ull; acc[i][1] = 0ull; }

    for (int c0 = 0; c0 < C; c0 += 16) {
        #pragma unroll
        for (int i = 0; i < 4; ++i) {
            int e = i*256 + tid;
            int cc = e & 15, r = e >> 4;
            Ws[cc][r] = W[(oT + r)*C + c0 + cc];
        }
        #pragma unroll
        for (int i = 0; i < 8; ++i) {
            int e = i*256 + tid;
            int cc = e & 15, r = e >> 4;
            Xs[cc][r] = X[(pT + r)*C + c0 + cc];
        }
        __syncthreads();
        #pragma unroll
        for (int cc = 0; cc < 16; ++cc) {
            ulonglong2 wq = *reinterpret_cast<const ulonglong2*>(&Ws[cc][tx*4]);
            float4 xa = *reinterpret_cast<const float4*>(&Xs[cc][ty*8]);
            float4 xb = *reinterpret_cast<const float4*>(&Xs[cc][ty*8 + 4]);
            u64 xp;
            xp = pack2(xa.x, xa.x); fma2(acc[0][0], xp, wq.x); fma2(acc[0][1], xp, wq.y);
            xp = pack2(xa.y, xa.y); fma2(acc[1][0], xp, wq.x); fma2(acc[1][1], xp, wq.y);
            xp = pack2(xa.z, xa.z); fma2(acc[2][0], xp, wq.x); fma2(acc[2][1], xp, wq.y);
            xp = pack2(xa.w, xa.w); fma2(acc[3][0], xp, wq.x); fma2(acc[3][1], xp, wq.y);
            xp = pack2(xb.x, xb.x); fma2(acc[4][0], xp, wq.x); fma2(acc[4][1], xp, wq.y);
            xp = pack2(xb.y, xb.y); fma2(acc[5][0], xp, wq.x); fma2(acc[5][1], xp, wq.y);
            xp = pack2(xb.z, xb.z); fma2(acc[6][0], xp, wq.x); fma2(acc[6][1], xp, wq.y);
            xp = pack2(xb.w, xb.w); fma2(acc[7][0], xp, wq.x); fma2(acc[7][1], xp, wq.y);
        }
        __syncthreads();
    }

    const float bnsc = 1.f / sqrtf(1.0f + 1e-5f);
    int p0 = pT + ty*8;
    int o0 = oT + tx*4;
    #pragma unroll
    for (int i = 0; i < 8; ++i) {
        float vs[4];
        unpack2(vs[0], vs[1], acc[i][0]);
        unpack2(vs[2], vs[3], acc[i][1]);
        #pragma unroll
        for (int j = 0; j < 4; ++j) {
            float v = vs[j];
            int og = o0 + j;
            if (mode >= 1) v += bias[og];
            if (mode == 2) {
                v += extra[((p0 + i) >> extraShift)*extraLd + og];
                v = fmaxf(v, 0.f);
            } else if (mode == 3) {
                v = v * (bnG[og] * bnsc) + bnB[og];
                v = (v > 0.f) ? v : 0.01f * v;
            }
            vs[j] = v;
        }
        *reinterpret_cast<float4*>(&Y[(p0 + i)*O + o0]) =
            make_float4(vs[0], vs[1], vs[2], vs[3]);
    }
}

// ---------------- FPS: 512 thr/block, 16 pts/thread, packed f32x2 -------------
__global__ __launch_bounds__(512)
void k_fps(const float* __restrict__ x, float* __restrict__ out)
{
    extern __shared__ float sm[];
    float* s_px = sm;
    float* s_py = sm + NPTS;
    float* s_pz = sm + 2*NPTS;
    __shared__ float s_wv[16];
    __shared__ int   s_wi[16];
    __shared__ int   s_sel;

    int b = blockIdx.x, t = threadIdx.x;
    int lane = t & 31, warp = t >> 5;
    int base = t * 16;

    u64 px2[8], py2[8], pz2[8];
    float md[16];
    #pragma unroll
    for (int i = 0; i < 8; ++i) {
        int n0 = base + 2*i;
        const float* pa = &x[(b*NPTS + n0)*3];
        float ax = pa[0], ay = pa[1], az = pa[2];
        float bx2 = pa[3], by2 = pa[4], bz2 = pa[5];
        px2[i] = pack2(ax, bx2); py2[i] = pack2(ay, by2); pz2[i] = pack2(az, bz2);
        s_px[n0] = ax; s_px[n0+1] = bx2;
        s_py[n0] = ay; s_py[n0+1] = by2;
        s_pz[n0] = az; s_pz[n0+1] = bz2;
        md[2*i] = 1e10f; md[2*i+1] = 1e10f;
    }
    if (t == 0) s_sel = 0;
    __syncthreads();
    if (t == 0) {
        g_fps[b*MQ] = 0;
        float* o = &out[(b*MQ)*3];
        o[0] = s_px[0]; o[1] = s_py[0]; o[2] = s_pz[0];
    }

    for (int it = 1; it < MQ; ++it) {
        int sel = s_sel;
        float lx = s_px[sel], ly = s_py[sel], lz = s_pz[sel];
        u64 nlx = pack2(-lx, -lx), nly = pack2(-ly, -ly), nlz = pack2(-lz, -lz);
        float bv = -1e30f; int bi = 0x7fffffff;
        #pragma unroll
        for (int i = 0; i < 8; ++i) {
            u64 dx = add2(px2[i], nlx);
            u64 dy = add2(py2[i], nly);
            u64 dz = add2(pz2[i], nlz);
            u64 s = add2(add2(mul2(dx, dx), mul2(dy, dy)), mul2(dz, dz));
            float s0, s1; unpack2(s0, s1, s);
            float m0 = fminf(md[2*i],   s0); md[2*i]   = m0;
            float m1 = fminf(md[2*i+1], s1); md[2*i+1] = m1;
            if (m0 > bv) { bv = m0; bi = base + 2*i; }
            if (m1 > bv) { bv = m1; bi = base + 2*i + 1; }
        }
        #pragma unroll
        for (int off = 16; off > 0; off >>= 1) {
            float ov = __shfl_down_sync(FULLM, bv, off);
            int   oi = __shfl_down_sync(FULLM, bi, off);
            if (ov > bv || (ov == bv && oi < bi)) { bv = ov; bi = oi; }
        }
        if (lane == 0) { s_wv[warp] = bv; s_wi[warp] = bi; }
        __syncthreads();
        if (warp == 0) {
            bv = (lane < 16) ? s_wv[lane] : -1e30f;
            bi = (lane < 16) ? s_wi[lane] : 0x7fffffff;
            #pragma unroll
            for (int off = 8; off > 0; off >>= 1) {
                float ov = __shfl_down_sync(FULLM, bv, off);
                int   oi = __shfl_down_sync(FULLM, bi, off);
                if (ov > bv || (ov == bv && oi < bi)) { bv = ov; bi = oi; }
            }
            if (lane == 0) {
                s_sel = bi;
                g_fps[b*MQ + it] = bi;
                float* o = &out[(b*MQ + it)*3];
                o[0] = s_px[bi]; o[1] = s_py[bi]; o[2] = s_pz[bi];
            }
        }
        __syncthreads();
    }
}

// ---------------- KNN: warp per query; per-lane sorted top-17 + warp merge ----
__global__ __launch_bounds__(256)
void k_knn(const float* __restrict__ x)
{
    int wq = blockIdx.x*8 + (threadIdx.x >> 5);
    int lane = threadIdx.x & 31;
    int b = wq >> 10;
    int self = g_fps[wq];
    const float* qp = &x[(b*NPTS + self)*3];
    float qx = qp[0], qy = qp[1], qz = qp[2];
    float qs = __fadd_rn(__fadd_rn(__fmul_rn(qx, qx), __fmul_rn(qy, qy)), __fmul_rn(qz, qz));

    float v[KNN]; int id[KNN];
    #pragma unroll
    for (int j = 0; j < KNN; ++j) { v[j] = FLT_MAX; id[j] = 0x7fffffff; }

    for (int n = lane; n < NPTS; n += 32) {
        const float* p = &x[(b*NPTS + n)*3];
        float p0 = p[0], p1 = p[1], p2 = p[2];
        float dot = __fadd_rn(__fadd_rn(__fmul_rn(qx, p0), __fmul_rn(qy, p1)),
                              __fmul_rn(qz, p2));
        float sn = __fadd_rn(__fadd_rn(__fmul_rn(p0, p0), __fmul_rn(p1, p1)),
                             __fmul_rn(p2, p2));
        float d2 = __fsub_rn(__fadd_rn(qs, sn), __fmul_rn(2.0f, dot));
        if (d2 < v[KNN-1] || (d2 == v[KNN-1] && n < id[KNN-1])) {
            v[KNN-1] = d2; id[KNN-1] = n;
            #pragma unroll
            for (int j = KNN-1; j > 0; --j) {
                if (v[j] < v[j-1] || (v[j] == v[j-1] && id[j] < id[j-1])) {
                    float tv = v[j]; v[j] = v[j-1]; v[j-1] = tv;
                    int   ti = id[j]; id[j] = id[j-1]; id[j-1] = ti;
                }
            }
        }
    }
    for (int r = 0; r < KNN; ++r) {
        float cv = v[0]; int ci = id[0];
        float bv = cv;   int bi = ci;
        #pragma unroll
        for (int off = 16; off > 0; off >>= 1) {
            float ov = __shfl_xor_sync(FULLM, bv, off);
            int   oi = __shfl_xor_sync(FULLM, bi, off);
            if (ov < bv || (ov == bv && oi < bi)) { bv = ov; bi = oi; }
        }
        if (cv == bv && ci == bi) {
            #pragma unroll
            for (int j = 0; j < KNN-1; ++j) { v[j] = v[j+1]; id[j] = id[j+1]; }
            v[KNN-1] = FLT_MAX; id[KNN-1] = 0x7fffffff;
        }
        if (lane == 0) g_knn[wq*KNN + r] = bi;
    }
}

// ---------------- fused r-build + s2 layer1 (9->64, bn + leaky) ---------------
__global__ __launch_bounds__(128)
void k_build_s2l1(const float* __restrict__ x,
                  const float* __restrict__ w, const float* __restrict__ bias,
                  const float* __restrict__ bg, const float* __restrict__ bb)
{
    __shared__ float sw[576];
    __shared__ float sb[64], sg[64], sbb[64];
    int t = threadIdx.x;
    for (int i = t; i < 576; i += 128) sw[i] = w[i];
    if (t < 64) { sb[t] = bias[t]; sg[t] = bg[t]; sbb[t] = bb[t]; }
    __syncthreads();
    int i = blockIdx.x*128 + t;
    int q = i / KNN;
    int b = q >> 10;
    int dn = g_fps[q];
    int nn = g_knn[i];
    const float* dp = &x[(b*NPTS + dn)*3];
    const float* kp = &x[(b*NPTS + nn)*3];
    float rr[9];
    rr[0] = dp[0]; rr[1] = dp[1]; rr[2] = dp[2];
    rr[3] = kp[0]; rr[4] = kp[1]; rr[5] = kp[2];
    rr[6] = rr[0]-rr[3]; rr[7] = rr[1]-rr[4]; rr[8] = rr[2]-rr[5];
    const float bnsc = 1.f / sqrtf(1.0f + 1e-5f);
    #pragma unroll 4
    for (int o = 0; o < 64; ++o) {
        float a = sb[o];
        #pragma unroll
        for (int c = 0; c < 9; ++c) a = fmaf(sw[o*9 + c], rr[c], a);
        a = a * (sg[o] * bnsc) + sbb[o];
        a = (a > 0.f) ? a : 0.01f * a;
        g_hb1[i*64 + o] = a;
    }
}

// ---------------- feat0 gather (self neighbor features) -----------------------
__global__ void k_feat0()
{
    int i = blockIdx.x*256 + threadIdx.x;
    int q = i >> 8, c = i & 255;
    int b = q >> 10;
    float val;
    if (c < 128) {
        int n = g_knn[q*KNN];
        val = g_f[(b*NPTS + n)*128 + c];
    } else {
        val = g_r2[(q*KNN)*128 + (c - 128)];
    }
    g_feat0[i] = val;
}

// ---------------- attention: logits via u.feat + folded cc, softmax, sum -----
__global__ __launch_bounds__(256)
void k_att(const float* __restrict__ x, float* __restrict__ out)
{
    int wq = blockIdx.x*8 + (threadIdx.x >> 5);
    int lane = threadIdx.x & 31;
    int b = wq >> 10;

    const float* u  = &g_u[wq*256];
    const float* f0 = &g_feat0[wq*256];
    float uf[4], ur[4];
    #pragma unroll
    for (int t = 0; t < 4; ++t) { uf[t] = u[lane + 32*t]; ur[t] = u[128 + lane + 32*t]; }
    float cc = 0.f;
    #pragma unroll
    for (int t = 0; t < 8; ++t) cc += f0[lane + 32*t] * g_wc[lane + 32*t];
    #pragma unroll
    for (int off = 16; off > 0; off >>= 1) cc += __shfl_xor_sync(FULLM, cc, off);
    cc += g_c0;

    float logit = 0.f;
    for (int j = 1; j < KNN; ++j) {
        int n = g_knn[wq*KNN + j];
        const float* fp = &g_f[(b*NPTS + n)*128];
        const float* rp = &g_r2[(wq*KNN + j)*128];
        float a = 0.f;
        #pragma unroll
        for (int t = 0; t < 4; ++t) a = fmaf(uf[t], fp[lane + 32*t], a);
        #pragma unroll
        for (int t = 0; t < 4; ++t) a = fmaf(ur[t], rp[lane + 32*t], a);
        #pragma unroll
        for (int off = 16; off > 0; off >>= 1) a += __shfl_xor_sync(FULLM, a, off);
        if (lane == j - 1) logit = a + cc;
    }
    float lv = (lane < 16) ? logit : -FLT_MAX;
    float mx = lv;
    #pragma unroll
    for (int off = 16; off > 0; off >>= 1) mx = fmaxf(mx, __shfl_xor_sync(FULLM, mx, off));
    float e = (lane < 16) ? expf(lv - mx) : 0.f;
    float s = e;
    #pragma unroll
    for (int off = 16; off > 0; off >>= 1) s += __shfl_xor_sync(FULLM, s, off);
    float w = e / s;

    float ox = 0.f, oy = 0.f, oz = 0.f;
    if (lane < 16) {
        int n = g_knn[wq*KNN + 1 + lane];
        const float* p = &x[(b*NPTS + n)*3];
        ox = w * p[0]; oy = w * p[1]; oz = w * p[2];
    }
    #pragma unroll
    for (int off = 16; off > 0; off >>= 1) {
        ox += __shfl_xor_sync(FULLM, ox, off);
        oy += __shfl_xor_sync(FULLM, oy, off);
        oz += __shfl_xor_sync(FULLM, oz, off);
    }
    if (lane == 0) {
        float* o = &out[(NQ + wq)*3];
        o[0] = ox; o[1] = oy; o[2] = oz;
    }
}

// ---------------- host side ---------------------------------------------------
static float* symf(const void* s) { void* p = 0; cudaGetSymbolAddress(&p, s); return (float*)p; }

extern "C" void kernel_launch(void* const* d_in, const int* in_sizes, int n_in,
                              void* d_out, int out_size)
{
    const float* x     = (const float*)d_in[0];
    const float* gfeat = (const float*)d_in[1];
    const float* c1_w1 = (const float*)d_in[2];
    const float* c1_b1 = (const float*)d_in[3];
    const float* c1_w2 = (const float*)d_in[4];
    const float* c1_b2 = (const float*)d_in[5];
    const float* cf_w1 = (const float*)d_in[6];
    const float* cf_b1 = (const float*)d_in[7];
    const float* cf_w2 = (const float*)d_in[8];
    const float* cf_b2 = (const float*)d_in[9];
    const float* cs_w1 = (const float*)d_in[10];
    const float* cs_b1 = (const float*)d_in[11];
    const float* cs_w2 = (const float*)d_in[12];
    const float* cs_b2 = (const float*)d_in[13];
    const float* s2_w1 = (const float*)d_in[14];
    const float* s2_b1 = (const float*)d_in[15];
    const float* s2_g1 = (const float*)d_in[16];
    const float* s2_bb1= (const float*)d_in[17];
    const float* s2_w2 = (const float*)d_in[18];
    const float* s2_b2 = (const float*)d_in[19];
    const float* s2_g2 = (const float*)d_in[20];
    const float* s2_bb2= (const float*)d_in[21];
    const float* s2_w3 = (const float*)d_in[22];
    const float* s2_b3 = (const float*)d_in[23];
    const float* q_w   = (const float*)d_in[24];
    const float* q_b   = (const float*)d_in[25];
    const float* k_w   = (const float*)d_in[26];
    const float* k_b   = (const float*)d_in[27];
    float* out = (float*)d_out;

    float* p_h1  = symf(g_h1);
    float* p_t   = symf(g_t);
    float* p_f   = symf(g_f);
    float* p_hb1 = symf(g_hb1);
    float* p_hb2 = symf(g_hb2);
    float* p_r2  = symf(g_r2);
    float* p_f0  = symf(g_feat0);
    float* p_u   = symf(g_u);
    float* p_cb  = symf(g_cb);
    float* p_Wa  = symf(g_Wa);
    float* p_ba  = symf(g_ba);
    float* p_A   = symf(g_A);
    float* p_u0  = symf(g_u0);

    static cudaStream_t sB = 0;
    static cudaEvent_t evF = 0, evJ = 0;
    static int inited = 0;
    if (!inited) {
        cudaFuncSetAttribute(k_fps, cudaFuncAttributeMaxDynamicSharedMemorySize, 3*NPTS*4);
        cudaStreamCreateWithFlags(&sB, cudaStreamNonBlocking);
        cudaEventCreateWithFlags(&evF, cudaEventDisableTiming);
        cudaEventCreateWithFlags(&evJ, cudaEventDisableTiming);
        inited = 1;
    }

    // ---- fork: stream B runs the FPS/KNN/grouped-conv chain ----
    cudaEventRecord(evF, 0);
    cudaStreamWaitEvent(sB, evF, 0);

    k_fps<<<NB, 512, 3*NPTS*4, sB>>>(x, out);
    k_knn<<<NQ/8, 256, 0, sB>>>(x);
    k_build_s2l1<<<NPOS/128, 128, 0, sB>>>(x, s2_w1, s2_b1, s2_g1, s2_bb1);
    // hb2 = lrelu(bn(s2_w2 @ hb1 + s2_b2))   (NPOS x 64)
    k_gemm<<<dim3(NPOS/128, 1), 256, 0, sB>>>(s2_w2, p_hb1, p_hb2, s2_b2,
                                              nullptr, 0, 0, s2_g2, s2_bb2, 64, 64, 3);
    // r2 = s2_w3 @ hb2 + s2_b3               (NPOS x 128)
    k_gemm<<<dim3(NPOS/128, 2), 256, 0, sB>>>(s2_w3, p_hb2, p_r2, s2_b3,
                                              nullptr, 0, 0, nullptr, nullptr, 64, 128, 1);

    // ---- stream 0: per-point feature chain (independent of FPS) ----
    k_pre_batch<<<NB, 256>>>(gfeat, cf_w1, cf_b1, cf_w2, cf_b2, cs_w1, cs_b1);
    k_pre_fold<<<65, 256>>>(cs_w1, c1_w2, c1_b2);
    k_pre_att<<<257, 256>>>(q_w, q_b, k_w, k_b);
    k_h1<<<NPB/128, 128>>>(x, c1_w1, c1_b1);
    // t = relu(Wa @ h1 + ba + cb[batch])     (NPB x 256)
    k_gemm<<<dim3(NPB/128, 4), 256>>>(p_Wa, p_h1, p_t, p_ba,
                                      p_cb, 13, 256, nullptr, nullptr, 64, 256, 2);
    // f = cs_w2 @ t + cs_b2                  (NPB x 128)
    k_gemm<<<dim3(NPB/128, 2), 256>>>(cs_w2, p_t, p_f, cs_b2,
                                      nullptr, 0, 0, nullptr, nullptr, 256, 128, 1);

    // ---- join: tail needs f (stream 0) + knn/r2 (stream B) ----
    cudaEventRecord(evJ, sB);
    cudaStreamWaitEvent(0, evJ, 0);

    k_feat0<<<NQ*256/256, 256>>>();
    // u = A @ feat0 + u0                     (NQ x 256)
    k_gemm<<<dim3(NQ/128, 4), 256>>>(p_A, p_f0, p_u, p_u0,
                                     nullptr, 0, 0, nullptr, nullptr, 256, 256, 1);
    k_att<<<NQ/8, 256>>>(x, out);
}